// round 14
// baseline (speedup 1.0000x reference)
#include <cuda_runtime.h>
#include <cuda_bf16.h>
#include <cstdint>

using bf16 = __nv_bfloat16;

namespace {
constexpr int BATCH=8, NA=1024, ND=4096, C=512, CI=256;
constexpr int RA=BATCH*NA, RD=BATCH*ND;
constexpr int RT=RD+RA;                    // 40960 concat rows [det|aim]
constexpr float EPS=1e-3f;
constexpr int SPLITK=8;
constexpr int NSTAGE=5;
constexpr int STAGE_B = 16384;             // k16 stage: AH4K|AL4K|BH4K|BL4K
constexpr int SMEM_BYTES = NSTAGE*STAGE_B; // 80KB
}

// ---- bf16 hi/lo split buffers (bss) ----
__device__ __align__(16) bf16 g_inH[(long)RT*C],  g_inL[(long)RT*C];    // [det|aim]
__device__ __align__(16) bf16 g_WgH[C*CI], g_WgL[C*CI];
__device__ __align__(16) bf16 g_WtH[C*CI], g_WtL[C*CI];
__device__ __align__(16) bf16 g_WpH[C*CI], g_WpL[C*CI];
__device__ __align__(16) bf16 g_WwH[CI*C], g_WwL[CI*C];
__device__ __align__(16) bf16 g_WqH[CI*C], g_WqL[CI*C];
__device__ __align__(16) bf16 g_dpH[(long)RT*512], g_dpL[(long)RT*512]; // [dx|ph] / [ax|th]
__device__ __align__(16) float g_p1[(long)BATCH*SPLITK*CI*CI];
__device__ __align__(16) float g_p2[(long)BATCH*SPLITK*CI*CI];
__device__ __align__(16) bf16 g_m1H[(long)BATCH*CI*CI], g_m1L[(long)BATCH*CI*CI];
__device__ __align__(16) bf16 g_m2H[(long)BATCH*CI*CI], g_m2L[(long)BATCH*CI*CI];
__device__ __align__(16) bf16 g_m1sH[(long)BATCH*CI*C], g_m1sL[(long)BATCH*CI*C];
__device__ __align__(16) bf16 g_m2sH[(long)BATCH*CI*C], g_m2sL[(long)BATCH*CI*C];
__device__ float g_svw[C], g_bvw[C], g_svq[C], g_bvq[C];

__device__ __forceinline__ void mma_bf16(float* c, const uint32_t* a, uint32_t b0, uint32_t b1){
    asm volatile("mma.sync.aligned.m16n8k16.row.col.f32.bf16.bf16.f32 "
        "{%0,%1,%2,%3},{%4,%5,%6,%7},{%8,%9},{%0,%1,%2,%3};\n"
        : "+f"(c[0]),"+f"(c[1]),"+f"(c[2]),"+f"(c[3])
        : "r"(a[0]),"r"(a[1]),"r"(a[2]),"r"(a[3]),"r"(b0),"r"(b1));
}
__device__ __forceinline__ void ldsm4(uint32_t* r, uint32_t a){
    asm volatile("ldmatrix.sync.aligned.m8n8.x4.shared.b16 {%0,%1,%2,%3},[%4];"
        : "=r"(r[0]),"=r"(r[1]),"=r"(r[2]),"=r"(r[3]) : "r"(a));
}
__device__ __forceinline__ void ldsm4t(uint32_t* r, uint32_t a){
    asm volatile("ldmatrix.sync.aligned.m8n8.x4.trans.shared.b16 {%0,%1,%2,%3},[%4];"
        : "=r"(r[0]),"=r"(r[1]),"=r"(r[2]),"=r"(r[3]) : "r"(a));
}
__device__ __forceinline__ void cpa16(uint32_t dst, const void* src){
    asm volatile("cp.async.cg.shared.global [%0], [%1], 16;" :: "r"(dst),"l"(src));
}
#define CP_COMMIT() asm volatile("cp.async.commit_group;")
#define CP_WAIT3()  asm volatile("cp.async.wait_group 3;")

// CTA tile 128x128, k-chunk 16, 5 stages, 128 threads = 4 warps (2x2), warp tile 64x64.
// MODE: 1 v+=biasv[col], 2 v*=scale, 4 v*=biasv[col], 5 v+=biasv[col]+resid[gidx]
template<int MODE, bool TA, bool OUTB>
__device__ __forceinline__ void gemm_body(
    const bf16* __restrict__ AH, const bf16* __restrict__ AL,
    const bf16* __restrict__ BH, const bf16* __restrict__ BL,
    float* __restrict__ Cf, bf16* __restrict__ CH, bf16* __restrict__ CL,
    const float* __restrict__ biasv, const float* __restrict__ resid, float scale,
    int K, long lda, long ldb, long ldc, int m0, int n0, int nB)
{
    extern __shared__ __align__(128) char smem[];
    const int tid=threadIdx.x, lane=tid&31, warp=tid>>5;   // 4 warps
    const uint32_t sb = (uint32_t)__cvta_generic_to_shared(smem);

    // ---- cp.async indexing: 8 x 16B per thread per stage ----
    long oA0, oA1; uint32_t dA0, dA1;
    if (!TA){
        const int row = tid;                 // 0..127, two k8 halves each
        oA0 = (long)(m0+row)*lda;
        oA1 = oA0 + 8;
        dA0 = (uint32_t)(row*2 + (0 ^ ((row>>2)&1)))*16;
        dA1 = (uint32_t)(row*2 + (1 ^ ((row>>2)&1)))*16;
    } else {
        const int k0_=tid>>4, m80=tid&15;    // slots tid, tid+128
        const int k1_=k0_+8;
        oA0 = (long)k0_*lda + m0 + m80*8;
        oA1 = (long)k1_*lda + m0 + m80*8;
        dA0 = (uint32_t)(k0_*16 + (m80 ^ (k0_&7)))*16;
        dA1 = (uint32_t)(k1_*16 + (m80 ^ (k1_&7)))*16;
    }
    const long stepA = TA ? 16*lda : 16;
    const int bk0=tid>>4, bn8=tid&15;        // slots tid, tid+128
    const int bk1=bk0+8;
    const long oB0 = (long)bk0*ldb + nB + bn8*8;
    const long oB1 = (long)bk1*ldb + nB + bn8*8;
    const uint32_t dB0 = (uint32_t)(bk0*16 + (bn8 ^ (bk0&7)))*16;
    const uint32_t dB1 = (uint32_t)(bk1*16 + (bn8 ^ (bk1&7)))*16;
    const long stepB = 16*ldb;

#define FILL(S, cc) { const uint32_t ba = sb + (S)*STAGE_B; const long kk=(long)(cc); \
    cpa16(ba        +dA0, AH+oA0+kk*stepA); cpa16(ba        +dA1, AH+oA1+kk*stepA); \
    cpa16(ba + 4096 +dA0, AL+oA0+kk*stepA); cpa16(ba + 4096 +dA1, AL+oA1+kk*stepA); \
    cpa16(ba + 8192 +dB0, BH+oB0+kk*stepB); cpa16(ba + 8192 +dB1, BH+oB1+kk*stepB); \
    cpa16(ba + 12288+dB0, BL+oB0+kk*stepB); cpa16(ba + 12288+dB1, BL+oB1+kk*stepB); }

    // ---- ldsm indexing: warp grid 2x2, warp tile 64x64 ----
    const int wm0 = (warp>>1)*64, wn0 = (warp&1)*64;
    const int g = lane>>3;
    int aCh[4];
#pragma unroll
    for (int mt=0; mt<4; mt++){
        if (!TA){
            const int row = wm0 + mt*16 + (lane&7) + (g&1)*8;
            aCh[mt] = row*2 + ((g>>1) ^ ((row>>2)&1));
        } else {
            const int row = (lane&7) + (g>>1)*8;
            const int c = ((wm0 + mt*16)>>3) + (g&1);
            aCh[mt] = row*16 + (c ^ (row&7));
        }
    }
    int bCh[4];
#pragma unroll
    for (int np=0; np<4; np++){
        const int row = (lane&7) + (g&1)*8;
        const int c = ((wn0 + np*16)>>3) + (g>>1);
        bCh[np] = row*16 + (c ^ (row&7));
    }

    float acc[4][8][4];
#pragma unroll
    for (int mt=0;mt<4;mt++)
#pragma unroll
        for (int nt=0;nt<8;nt++)
#pragma unroll
            for (int i=0;i<4;i++) acc[mt][nt][i]=0.f;

    const int NC = K>>4;
#pragma unroll
    for (int c=0; c<4; c++){ FILL(c, c); CP_COMMIT(); }

    int sidx = 0, fidx = 4;
#pragma unroll 1
    for (int c=0; c<NC; c++){
        CP_WAIT3();
        __syncthreads();
        if (c+4 < NC){ FILL(fidx, c+4); }
        CP_COMMIT();

        const uint32_t ba = sb + sidx*STAGE_B;
        uint32_t Ah[4][4], Al[4][4];
#pragma unroll
        for (int mt=0; mt<4; mt++){
            if (!TA){
                ldsm4 (Ah[mt], ba + aCh[mt]*16);
                ldsm4 (Al[mt], ba + 4096 + aCh[mt]*16);
            } else {
                ldsm4t(Ah[mt], ba + aCh[mt]*16);
                ldsm4t(Al[mt], ba + 4096 + aCh[mt]*16);
            }
        }
#pragma unroll
        for (int np=0; np<4; np++){
            uint32_t Bh[4], Bl[4];
            ldsm4t(Bh, ba + 8192  + bCh[np]*16);
            ldsm4t(Bl, ba + 12288 + bCh[np]*16);
            const int n2 = np*2;
#pragma unroll
            for (int mt=0; mt<4; mt++){
                mma_bf16(acc[mt][n2],   Ah[mt], Bh[0], Bh[1]);
                mma_bf16(acc[mt][n2+1], Ah[mt], Bh[2], Bh[3]);
                mma_bf16(acc[mt][n2],   Ah[mt], Bl[0], Bl[1]);
                mma_bf16(acc[mt][n2+1], Ah[mt], Bl[2], Bl[3]);
                mma_bf16(acc[mt][n2],   Al[mt], Bh[0], Bh[1]);
                mma_bf16(acc[mt][n2+1], Al[mt], Bh[2], Bh[3]);
            }
        }
        sidx = (sidx+1 == NSTAGE) ? 0 : sidx+1;
        fidx = (fidx+1 == NSTAGE) ? 0 : fidx+1;
    }
#undef FILL

    const int rbase = m0 + wm0 + (lane>>2);
    const int cbase = n0 + wn0 + (lane&3)*2;
#pragma unroll
    for (int mt=0; mt<4; mt++){
#pragma unroll
        for (int nt=0; nt<8; nt++){
            const int col = cbase + nt*8;
#pragma unroll
            for (int hf=0; hf<2; hf++){
                const int row = rbase + mt*16 + hf*8;
                float v0 = acc[mt][nt][hf*2];
                float v1 = acc[mt][nt][hf*2+1];
                const long gidx = (long)row*ldc + col;
                if (MODE==1){ v0 += biasv[col]; v1 += biasv[col+1]; }
                if (MODE==2){ v0 *= scale; v1 *= scale; }
                if (MODE==4){ v0 *= biasv[col]; v1 *= biasv[col+1]; }
                if (MODE==5){
                    const float2 rr = *(const float2*)&resid[gidx];
                    v0 += biasv[col]   + rr.x;
                    v1 += biasv[col+1] + rr.y;
                }
                if (OUTB){
                    const bf16 h0 = __float2bfloat16_rn(v0);
                    const bf16 h1 = __float2bfloat16_rn(v1);
                    const bf16 l0 = __float2bfloat16_rn(v0 - __bfloat162float(h0));
                    const bf16 l1 = __float2bfloat16_rn(v1 - __bfloat162float(h1));
                    __nv_bfloat162 hp = {h0,h1}, lp = {l0,l1};
                    *(uint32_t*)&CH[gidx] = *(uint32_t*)&hp;
                    *(uint32_t*)&CL[gidx] = *(uint32_t*)&lp;
                } else {
                    *(float2*)&Cf[gidx] = make_float2(v0, v1);
                }
            }
        }
    }
}

// merged projection: [dx|ph / ax|th] = [det|aim] @ {Wg, Wp-or-Wt} + bias
__global__ __launch_bounds__(128,2) void k_proj(
    const bf16* __restrict__ inH, const bf16* __restrict__ inL,
    const bf16* __restrict__ WgH, const bf16* __restrict__ WgL,
    const bf16* __restrict__ WpH, const bf16* __restrict__ WpL,
    const bf16* __restrict__ WtH, const bf16* __restrict__ WtL,
    bf16* dpH, bf16* dpL,
    const float* bg, const float* bp, const float* bt)
{
    const int y = blockIdx.y, n0 = blockIdx.x*128;
    const bool aimrow = (y >= RD/128);
    const bf16 *BH, *BL; const float* bias;
    if (n0 < 256){ BH=WgH; BL=WgL; bias=bg; }
    else if (!aimrow){ BH=WpH; BL=WpL; bias=bp-256; }
    else { BH=WtH; BL=WtL; bias=bt-256; }
    const int nB = (n0<256)? n0 : n0-256;
    gemm_body<1,false,true>(inH,inL, BH,BL, nullptr,dpH,dpL,
        bias,nullptr,0.f, C, C,CI,512, y*128, n0, nB);
}

// merged gram: m1 = ph^T dx / ND (z<64), m2 = th^T ax / NA (z>=64), SPLITK=8
__global__ __launch_bounds__(128,2) void k_gram(
    const bf16* __restrict__ dpH, const bf16* __restrict__ dpL,
    float* p1, float* p2)
{
    const int z = blockIdx.z;
    const bool is2 = (z >= BATCH*SPLITK);
    const int zz = is2? z-BATCH*SPLITK : z;
    const int b = zz/SPLITK, s = zz%SPLITK;
    long arow; int K; float* P; float scale;
    if (!is2){ arow = (long)b*ND + (long)s*(ND/SPLITK); K = ND/SPLITK; P = p1; scale = 1.f/(float)ND; }
    else     { arow = (long)RD + (long)b*NA + (long)s*(NA/SPLITK); K = NA/SPLITK; P = p2; scale = 1.f/(float)NA; }
    gemm_body<2,true,false>(dpH + arow*512 + 256, dpL + arow*512 + 256,
        dpH + arow*512, dpL + arow*512,
        P + (long)zz*CI*CI, nullptr, nullptr,
        nullptr,nullptr, scale, K, 512,512,CI,
        blockIdx.y*128, blockIdx.x*128, blockIdx.x*128);
}

// merged fold: m1s = (m1 @ Ww)*svw (z<8), m2s = (m2 @ Wq)*svq (z>=8)
__global__ __launch_bounds__(128,2) void k_fold(
    const bf16* m1H,const bf16* m1L,const bf16* m2H,const bf16* m2L,
    const bf16* WwH,const bf16* WwL,const bf16* WqH,const bf16* WqL,
    bf16* m1sH,bf16* m1sL,bf16* m2sH,bf16* m2sL,
    const float* svw,const float* svq)
{
    const int z = blockIdx.z;
    const bool q = (z >= BATCH);
    const int b = q? z-BATCH : z;
    const long aoff = (long)b*CI*CI, coff = (long)b*CI*C;
    gemm_body<4,false,true>(
        (q?m2H:m1H)+aoff, (q?m2L:m1L)+aoff,
        q?WqH:WwH, q?WqL:WwL,
        nullptr, (q?m2sH:m1sH)+coff, (q?m2sL:m1sL)+coff,
        q?svq:svw, nullptr, 0.f, CI, CI,C,C,
        blockIdx.y*128, blockIdx.x*128, blockIdx.x*128);
}

// merged outputs: y<32: out_nd = ph@m2s + bvq + detect ; y>=32: out_na = th@m1s + bvw + aim
__global__ __launch_bounds__(128,2) void k_out(
    const bf16* __restrict__ dpH, const bf16* __restrict__ dpL,
    const bf16* m1sH,const bf16* m1sL,const bf16* m2sH,const bf16* m2sL,
    float* out_na, float* out_nd, const float* aim, const float* detect,
    const float* bvw,const float* bvq)
{
    const int z = blockIdx.z, y = blockIdx.y;
    const bool na = (y >= ND/128);
    long arow; float* Cf; const float* resid; const bf16 *BH,*BL; const float* bias; int m0;
    if (!na){
        arow = (long)z*ND; m0 = y*128;
        Cf = out_nd + (long)z*ND*C; resid = detect + (long)z*ND*C;
        BH = m2sH + (long)z*CI*C; BL = m2sL + (long)z*CI*C; bias = bvq;
    } else {
        arow = (long)RD + (long)z*NA; m0 = (y - ND/128)*128;
        Cf = out_na + (long)z*NA*C; resid = aim + (long)z*NA*C;
        BH = m1sH + (long)z*CI*C; BL = m1sL + (long)z*CI*C; bias = bvw;
    }
    gemm_body<5,false,false>(dpH + arow*512 + 256, dpL + arow*512 + 256,
        BH,BL, Cf,nullptr,nullptr, bias, resid, 0.f,
        CI, 512,C,C, m0, blockIdx.x*128, blockIdx.x*128);
}

// one launch splits BOTH inputs into the contiguous [det|aim] buffer
__global__ __launch_bounds__(256) void insplit(const float* __restrict__ det,
                                               const float* __restrict__ aim,
                                               bf16* __restrict__ h, bf16* __restrict__ l){
    const long i = (long)blockIdx.x*256 + threadIdx.x;      // over RT*C/4
    if (i >= (long)RT*C/4) return;
    const long dlim = (long)RD*C/4;
    const float4 v = (i < dlim) ? ((const float4*)det)[i] : ((const float4*)aim)[i - dlim];
    const float f[4] = {v.x,v.y,v.z,v.w};
    bf16 hh[4], ll[4];
#pragma unroll
    for (int j=0;j<4;j++){
        hh[j] = __float2bfloat16_rn(f[j]);
        ll[j] = __float2bfloat16_rn(f[j] - __bfloat162float(hh[j]));
    }
    ((uint2*)h)[i] = *(uint2*)hh;
    ((uint2*)l)[i] = *(uint2*)ll;
}

struct SplitPack { const float* s[5]; bf16* h[5]; bf16* l[5]; };
__global__ __launch_bounds__(256) void fsplitN(SplitPack p, int n4){
    const int a = blockIdx.y;
    const int i = blockIdx.x*256 + threadIdx.x;
    if (i >= n4) return;
    const float4 v = ((const float4*)p.s[a])[i];
    const float f[4] = {v.x,v.y,v.z,v.w};
    bf16 hh[4], ll[4];
#pragma unroll
    for (int j=0;j<4;j++){
        hh[j] = __float2bfloat16_rn(f[j]);
        ll[j] = __float2bfloat16_rn(f[j] - __bfloat162float(hh[j]));
    }
    ((uint2*)p.h[a])[i] = *(uint2*)hh;
    ((uint2*)p.l[a])[i] = *(uint2*)ll;
}

__global__ void reduce8b2(const float* __restrict__ pa, bf16* __restrict__ oha, bf16* __restrict__ ola,
                          const float* __restrict__ pb, bf16* __restrict__ ohb, bf16* __restrict__ olb){
    const int nper = CI*CI;
    const int i = blockIdx.x*blockDim.x + threadIdx.x;
    if (i >= BATCH*nper) return;
    const int b = i/nper, r = i - b*nper;
    const float* p = (blockIdx.y ? pb : pa) + (long)b*SPLITK*nper + r;
    float s = 0.f;
#pragma unroll
    for (int k=0;k<SPLITK;k++) s += p[(long)k*nper];
    const bf16 h = __float2bfloat16_rn(s);
    if (blockIdx.y){ ohb[i] = h; olb[i] = __float2bfloat16_rn(s - __bfloat162float(h)); }
    else           { oha[i] = h; ola[i] = __float2bfloat16_rn(s - __bfloat162float(h)); }
}

__global__ void prep(const float* gw,const float* betw,const float* mw,const float* vw,const float* bw,
                     const float* gq,const float* betq,const float* mq,const float* vq,const float* bq,
                     float* svw,float* bvw,float* svq,float* bvq){
    const int i = threadIdx.x;  // 512
    const float s = gw[i]*rsqrtf(vw[i]+EPS);
    svw[i] = s; bvw[i] = (bw[i]-mw[i])*s + betw[i];
    const float t = gq[i]*rsqrtf(vq[i]+EPS);
    svq[i] = t; bvq[i] = (bq[i]-mq[i])*t + betq[i];
}

#define SYM(p, s) cudaGetSymbolAddress((void**)&p, s)

extern "C" void kernel_launch(void* const* d_in, const int* in_sizes, int n_in,
                              void* d_out, int out_size){
    (void)in_sizes; (void)n_in; (void)out_size;
    const float* detect=(const float*)d_in[0];
    const float* aim   =(const float*)d_in[1];
    const float* Wg=(const float*)d_in[2];  const float* bg=(const float*)d_in[3];
    const float* Wt=(const float*)d_in[4];  const float* bt=(const float*)d_in[5];
    const float* Wp=(const float*)d_in[6];  const float* bp=(const float*)d_in[7];
    const float* Ww=(const float*)d_in[8];  const float* bw=(const float*)d_in[9];
    const float* gw=(const float*)d_in[10]; const float* betw=(const float*)d_in[11];
    const float* mw=(const float*)d_in[12]; const float* vw=(const float*)d_in[13];
    const float* Wq=(const float*)d_in[14]; const float* bq=(const float*)d_in[15];
    const float* gq=(const float*)d_in[16]; const float* betq=(const float*)d_in[17];
    const float* mq=(const float*)d_in[18]; const float* vq=(const float*)d_in[19];

    float* out    = (float*)d_out;
    float* out_na = out;
    float* out_nd = out + (long)RA*C;

    bf16 *inH,*inL,*WgH,*WgL,*WtH,*WtL,*WpH,*WpL,*WwH,*WwL,*WqH,*WqL;
    bf16 *dpH,*dpL,*m1H,*m1L,*m2H,*m2L,*m1sH,*m1sL,*m2sH,*m2sL;
    float *p1,*p2,*svw,*bvw,*svq,*bvq;
    SYM(inH,g_inH); SYM(inL,g_inL);
    SYM(WgH,g_WgH); SYM(WgL,g_WgL); SYM(WtH,g_WtH); SYM(WtL,g_WtL);
    SYM(WpH,g_WpH); SYM(WpL,g_WpL); SYM(WwH,g_WwH); SYM(WwL,g_WwL);
    SYM(WqH,g_WqH); SYM(WqL,g_WqL);
    SYM(dpH,g_dpH); SYM(dpL,g_dpL);
    SYM(m1H,g_m1H); SYM(m1L,g_m1L); SYM(m2H,g_m2H); SYM(m2L,g_m2L);
    SYM(m1sH,g_m1sH); SYM(m1sL,g_m1sL); SYM(m2sH,g_m2sH); SYM(m2sL,g_m2sL);
    SYM(p1,g_p1); SYM(p2,g_p2);
    SYM(svw,g_svw); SYM(bvw,g_bvw); SYM(svq,g_svq); SYM(bvq,g_bvq);

    cudaFuncSetAttribute(k_proj, cudaFuncAttributeMaxDynamicSharedMemorySize, SMEM_BYTES);
    cudaFuncSetAttribute(k_gram, cudaFuncAttributeMaxDynamicSharedMemorySize, SMEM_BYTES);
    cudaFuncSetAttribute(k_fold, cudaFuncAttributeMaxDynamicSharedMemorySize, SMEM_BYTES);
    cudaFuncSetAttribute(k_out,  cudaFuncAttributeMaxDynamicSharedMemorySize, SMEM_BYTES);

    const dim3 blk(128);

    // #1 merged input split, #2 weights, #3 prep, #4 PROJ (ncu target)
    insplit<<<(int)(((long)RT*C/4+255)/256), 256>>>(detect, aim, inH, inL);
    {
        SplitPack sp{{Wg,Wp,Wt,Ww,Wq},{WgH,WpH,WtH,WwH,WqH},{WgL,WpL,WtL,WwL,WqL}};
        fsplitN<<<dim3((C*CI/4+255)/256,5), 256>>>(sp, C*CI/4);
    }
    prep<<<1,512>>>(gw,betw,mw,vw,bw, gq,betq,mq,vq,bq, svw,bvw,svq,bvq);

    k_proj<<<dim3(4, RT/128, 1), blk, SMEM_BYTES>>>(inH,inL, WgH,WgL, WpH,WpL, WtH,WtL,
        dpH,dpL, bg,bp,bt);

    k_gram<<<dim3(2,2,2*BATCH*SPLITK), blk, SMEM_BYTES>>>(dpH,dpL, p1,p2);
    reduce8b2<<<dim3((BATCH*CI*CI+255)/256,2),256>>>(p1,m1H,m1L, p2,m2H,m2L);

    k_fold<<<dim3(4,2,2*BATCH), blk, SMEM_BYTES>>>(m1H,m1L,m2H,m2L,
        WwH,WwL,WqH,WqL, m1sH,m1sL,m2sH,m2sL, svw,svq);

    k_out<<<dim3(4, ND/128 + NA/128, BATCH), blk, SMEM_BYTES>>>(dpH,dpL,
        m1sH,m1sL,m2sH,m2sL, out_na,out_nd, aim,detect, bvw,bvq);
}

// round 15
// speedup vs baseline: 1.2423x; 1.2423x over previous
#include <cuda_runtime.h>
#include <cuda_bf16.h>
#include <cstdint>

using bf16 = __nv_bfloat16;

namespace {
constexpr int BATCH=8, NA=1024, ND=4096, C=512, CI=256;
constexpr int RA=BATCH*NA, RD=BATCH*ND;
constexpr int RT=RD+RA;                    // 40960 concat rows [det|aim]
constexpr float EPS=1e-3f;
constexpr int SPLITK=8;
constexpr int NSTAGE=5;
constexpr int STAGE_B = 16384;             // k16 stage: AH4K|AL4K|BH4K|BL4K
constexpr int SMEM_BYTES = NSTAGE*STAGE_B; // 80KB
}

// ---- bf16 hi/lo split buffers (bss) ----
__device__ __align__(16) bf16 g_inH[(long)RT*C],  g_inL[(long)RT*C];    // [det|aim]
__device__ __align__(16) bf16 g_WgH[C*CI], g_WgL[C*CI];
__device__ __align__(16) bf16 g_WtH[C*CI], g_WtL[C*CI];
__device__ __align__(16) bf16 g_WpH[C*CI], g_WpL[C*CI];
__device__ __align__(16) bf16 g_WwH[CI*C], g_WwL[CI*C];
__device__ __align__(16) bf16 g_WqH[CI*C], g_WqL[CI*C];
__device__ __align__(16) bf16 g_dpH[(long)RT*512], g_dpL[(long)RT*512]; // [dx|ph] / [ax|th]
__device__ __align__(16) float g_p1[(long)BATCH*SPLITK*CI*CI];
__device__ __align__(16) float g_p2[(long)BATCH*SPLITK*CI*CI];
__device__ __align__(16) bf16 g_m1H[(long)BATCH*CI*CI], g_m1L[(long)BATCH*CI*CI];
__device__ __align__(16) bf16 g_m2H[(long)BATCH*CI*CI], g_m2L[(long)BATCH*CI*CI];
__device__ __align__(16) bf16 g_m1sH[(long)BATCH*CI*C], g_m1sL[(long)BATCH*CI*C];
__device__ __align__(16) bf16 g_m2sH[(long)BATCH*CI*C], g_m2sL[(long)BATCH*CI*C];
__device__ float g_svw[C], g_bvw[C], g_svq[C], g_bvq[C];

__device__ __forceinline__ void mma_bf16(float* c, const uint32_t* a, uint32_t b0, uint32_t b1){
    asm volatile("mma.sync.aligned.m16n8k16.row.col.f32.bf16.bf16.f32 "
        "{%0,%1,%2,%3},{%4,%5,%6,%7},{%8,%9},{%0,%1,%2,%3};\n"
        : "+f"(c[0]),"+f"(c[1]),"+f"(c[2]),"+f"(c[3])
        : "r"(a[0]),"r"(a[1]),"r"(a[2]),"r"(a[3]),"r"(b0),"r"(b1));
}
__device__ __forceinline__ void ldsm4(uint32_t* r, uint32_t a){
    asm volatile("ldmatrix.sync.aligned.m8n8.x4.shared.b16 {%0,%1,%2,%3},[%4];"
        : "=r"(r[0]),"=r"(r[1]),"=r"(r[2]),"=r"(r[3]) : "r"(a));
}
__device__ __forceinline__ void ldsm4t(uint32_t* r, uint32_t a){
    asm volatile("ldmatrix.sync.aligned.m8n8.x4.trans.shared.b16 {%0,%1,%2,%3},[%4];"
        : "=r"(r[0]),"=r"(r[1]),"=r"(r[2]),"=r"(r[3]) : "r"(a));
}
__device__ __forceinline__ void cpa16(uint32_t dst, const void* src){
    asm volatile("cp.async.cg.shared.global [%0], [%1], 16;" :: "r"(dst),"l"(src));
}
#define CP_COMMIT() asm volatile("cp.async.commit_group;")
#define CP_WAIT3()  asm volatile("cp.async.wait_group 3;")

// CTA tile 128x128, k-chunk 16, 5 stages, 8 warps (4x2), warp tile 32x64.
// MODE: 1 v+=biasv[col], 2 v*=scale, 4 v*=biasv[col], 5 v+=biasv[col]+resid[gidx]
template<int MODE, bool TA, bool OUTB>
__device__ __forceinline__ void gemm_body(
    const bf16* __restrict__ AH, const bf16* __restrict__ AL,
    const bf16* __restrict__ BH, const bf16* __restrict__ BL,
    float* __restrict__ Cf, bf16* __restrict__ CH, bf16* __restrict__ CL,
    const float* __restrict__ biasv, const float* __restrict__ resid, float scale,
    int K, long lda, long ldb, long ldc, int m0, int n0, int nB)
{
    extern __shared__ __align__(128) char smem[];
    const int tid=threadIdx.x, lane=tid&31, warp=tid>>5;
    const uint32_t sb = (uint32_t)__cvta_generic_to_shared(smem);

    const bf16 *pAH, *pAL;
    uint32_t dA; long stepA;
    if (!TA){
        const int row=tid>>1, k8=tid&1;
        const long o = (long)(m0+row)*lda + k8*8;
        pAH = AH+o; pAL = AL+o;
        dA = (uint32_t)(row*2 + (k8 ^ ((row>>2)&1)))*16;
        stepA = 16;
    } else {
        const int k=tid>>4, m8=tid&15;
        const long o = (long)k*lda + m0 + m8*8;
        pAH = AH+o; pAL = AL+o;
        dA = (uint32_t)(k*16 + (m8 ^ (k&7)))*16;
        stepA = 16*lda;
    }
    const int kb=tid>>4, n8=tid&15;
    const long oB = (long)kb*ldb + nB + n8*8;
    const bf16 *pBH = BH+oB, *pBL = BL+oB;
    const uint32_t dB = (uint32_t)(kb*16 + (n8 ^ (kb&7)))*16;
    const long stepB = 16*ldb;

    const int wm0 = (warp>>1)*32, wn0 = (warp&1)*64;
    const int g = lane>>3;
    int aCh[2];
#pragma unroll
    for (int mt=0; mt<2; mt++){
        if (!TA){
            const int row = wm0 + mt*16 + (lane&7) + (g&1)*8;
            aCh[mt] = row*2 + ((g>>1) ^ ((row>>2)&1));
        } else {
            const int row = (lane&7) + (g>>1)*8;
            const int c = ((wm0 + mt*16)>>3) + (g&1);
            aCh[mt] = row*16 + (c ^ (row&7));
        }
    }
    int bCh[4];
#pragma unroll
    for (int np=0; np<4; np++){
        const int row = (lane&7) + (g&1)*8;
        const int c = ((wn0 + np*16)>>3) + (g>>1);
        bCh[np] = row*16 + (c ^ (row&7));
    }

    float acc[2][8][4];
#pragma unroll
    for (int mt=0;mt<2;mt++)
#pragma unroll
        for (int nt=0;nt<8;nt++)
#pragma unroll
            for (int i=0;i<4;i++) acc[mt][nt][i]=0.f;

    const int NC = K>>4;
#pragma unroll
    for (int c=0; c<4; c++){
        const uint32_t ba = sb + c*STAGE_B;
        cpa16(ba         + dA, pAH + (long)c*stepA);
        cpa16(ba + 4096  + dA, pAL + (long)c*stepA);
        cpa16(ba + 8192  + dB, pBH + (long)c*stepB);
        cpa16(ba + 12288 + dB, pBL + (long)c*stepB);
        CP_COMMIT();
    }

    int sidx = 0, fidx = 4;
#pragma unroll 1
    for (int c=0; c<NC; c++){
        CP_WAIT3();
        __syncthreads();
        if (c+4 < NC){
            const uint32_t ba = sb + fidx*STAGE_B;
            cpa16(ba         + dA, pAH + (long)(c+4)*stepA);
            cpa16(ba + 4096  + dA, pAL + (long)(c+4)*stepA);
            cpa16(ba + 8192  + dB, pBH + (long)(c+4)*stepB);
            cpa16(ba + 12288 + dB, pBL + (long)(c+4)*stepB);
        }
        CP_COMMIT();

        const uint32_t ba = sb + sidx*STAGE_B;
        uint32_t Ah[2][4], Al[2][4];
#pragma unroll
        for (int mt=0; mt<2; mt++){
            if (!TA){
                ldsm4 (Ah[mt], ba + aCh[mt]*16);
                ldsm4 (Al[mt], ba + 4096 + aCh[mt]*16);
            } else {
                ldsm4t(Ah[mt], ba + aCh[mt]*16);
                ldsm4t(Al[mt], ba + 4096 + aCh[mt]*16);
            }
        }
#pragma unroll
        for (int np=0; np<4; np++){
            uint32_t Bh[4], Bl[4];
            ldsm4t(Bh, ba + 8192  + bCh[np]*16);
            ldsm4t(Bl, ba + 12288 + bCh[np]*16);
            const int n2 = np*2;
#pragma unroll
            for (int mt=0; mt<2; mt++){
                mma_bf16(acc[mt][n2],   Ah[mt], Bh[0], Bh[1]);
                mma_bf16(acc[mt][n2+1], Ah[mt], Bh[2], Bh[3]);
                mma_bf16(acc[mt][n2],   Ah[mt], Bl[0], Bl[1]);
                mma_bf16(acc[mt][n2+1], Ah[mt], Bl[2], Bl[3]);
                mma_bf16(acc[mt][n2],   Al[mt], Bh[0], Bh[1]);
                mma_bf16(acc[mt][n2+1], Al[mt], Bh[2], Bh[3]);
            }
        }
        sidx = (sidx+1 == NSTAGE) ? 0 : sidx+1;
        fidx = (fidx+1 == NSTAGE) ? 0 : fidx+1;
    }

    const int rbase = m0 + wm0 + (lane>>2);
    const int cbase = n0 + wn0 + (lane&3)*2;
#pragma unroll
    for (int mt=0; mt<2; mt++){
#pragma unroll
        for (int nt=0; nt<8; nt++){
            const int col = cbase + nt*8;
#pragma unroll
            for (int hf=0; hf<2; hf++){
                const int row = rbase + mt*16 + hf*8;
                float v0 = acc[mt][nt][hf*2];
                float v1 = acc[mt][nt][hf*2+1];
                const long gidx = (long)row*ldc + col;
                if (MODE==1){ v0 += biasv[col]; v1 += biasv[col+1]; }
                if (MODE==2){ v0 *= scale; v1 *= scale; }
                if (MODE==4){ v0 *= biasv[col]; v1 *= biasv[col+1]; }
                if (MODE==5){
                    const float2 rr = *(const float2*)&resid[gidx];
                    v0 += biasv[col]   + rr.x;
                    v1 += biasv[col+1] + rr.y;
                }
                if (OUTB){
                    const bf16 h0 = __float2bfloat16_rn(v0);
                    const bf16 h1 = __float2bfloat16_rn(v1);
                    const bf16 l0 = __float2bfloat16_rn(v0 - __bfloat162float(h0));
                    const bf16 l1 = __float2bfloat16_rn(v1 - __bfloat162float(h1));
                    __nv_bfloat162 hp = {h0,h1}, lp = {l0,l1};
                    *(uint32_t*)&CH[gidx] = *(uint32_t*)&hp;
                    *(uint32_t*)&CL[gidx] = *(uint32_t*)&lp;
                } else {
                    *(float2*)&Cf[gidx] = make_float2(v0, v1);
                }
            }
        }
    }
}

// merged projection: [dx|ph / ax|th] = [det|aim] @ {Wg, Wp-or-Wt} + bias
__global__ __launch_bounds__(256,2) void k_proj(
    const bf16* __restrict__ inH, const bf16* __restrict__ inL,
    const bf16* __restrict__ WgH, const bf16* __restrict__ WgL,
    const bf16* __restrict__ WpH, const bf16* __restrict__ WpL,
    const bf16* __restrict__ WtH, const bf16* __restrict__ WtL,
    bf16* dpH, bf16* dpL,
    const float* bg, const float* bp, const float* bt)
{
    const int y = blockIdx.y, n0 = blockIdx.x*128;
    const bool aimrow = (y >= RD/128);
    const bf16 *BH, *BL; const float* bias;
    if (n0 < 256){ BH=WgH; BL=WgL; bias=bg; }
    else if (!aimrow){ BH=WpH; BL=WpL; bias=bp-256; }
    else { BH=WtH; BL=WtL; bias=bt-256; }
    const int nB = (n0<256)? n0 : n0-256;
    gemm_body<1,false,true>(inH,inL, BH,BL, nullptr,dpH,dpL,
        bias,nullptr,0.f, C, C,CI,512, y*128, n0, nB);
}

// merged gram: m1 = ph^T dx / ND (z<64), m2 = th^T ax / NA (z>=64), SPLITK=8
__global__ __launch_bounds__(256,2) void k_gram(
    const bf16* __restrict__ dpH, const bf16* __restrict__ dpL,
    float* p1, float* p2)
{
    const int z = blockIdx.z;
    const bool is2 = (z >= BATCH*SPLITK);
    const int zz = is2? z-BATCH*SPLITK : z;
    const int b = zz/SPLITK, s = zz%SPLITK;
    long arow; int K; float* P; float scale;
    if (!is2){ arow = (long)b*ND + (long)s*(ND/SPLITK); K = ND/SPLITK; P = p1; scale = 1.f/(float)ND; }
    else     { arow = (long)RD + (long)b*NA + (long)s*(NA/SPLITK); K = NA/SPLITK; P = p2; scale = 1.f/(float)NA; }
    gemm_body<2,true,false>(dpH + arow*512 + 256, dpL + arow*512 + 256,
        dpH + arow*512, dpL + arow*512,
        P + (long)zz*CI*CI, nullptr, nullptr,
        nullptr,nullptr, scale, K, 512,512,CI,
        blockIdx.y*128, blockIdx.x*128, blockIdx.x*128);
}

// merged fold: m1s = (m1 @ Ww)*svw (z<8), m2s = (m2 @ Wq)*svq (z>=8)
__global__ __launch_bounds__(256,2) void k_fold(
    const bf16* m1H,const bf16* m1L,const bf16* m2H,const bf16* m2L,
    const bf16* WwH,const bf16* WwL,const bf16* WqH,const bf16* WqL,
    bf16* m1sH,bf16* m1sL,bf16* m2sH,bf16* m2sL,
    const float* svw,const float* svq)
{
    const int z = blockIdx.z;
    const bool q = (z >= BATCH);
    const int b = q? z-BATCH : z;
    const long aoff = (long)b*CI*CI, coff = (long)b*CI*C;
    gemm_body<4,false,true>(
        (q?m2H:m1H)+aoff, (q?m2L:m1L)+aoff,
        q?WqH:WwH, q?WqL:WwL,
        nullptr, (q?m2sH:m1sH)+coff, (q?m2sL:m1sL)+coff,
        q?svq:svw, nullptr, 0.f, CI, CI,C,C,
        blockIdx.y*128, blockIdx.x*128, blockIdx.x*128);
}

// merged outputs: y<32: out_nd = ph@m2s + bvq + detect ; y>=32: out_na = th@m1s + bvw + aim
__global__ __launch_bounds__(256,2) void k_out(
    const bf16* __restrict__ dpH, const bf16* __restrict__ dpL,
    const bf16* m1sH,const bf16* m1sL,const bf16* m2sH,const bf16* m2sL,
    float* out_na, float* out_nd, const float* aim, const float* detect,
    const float* bvw,const float* bvq)
{
    const int z = blockIdx.z, y = blockIdx.y;
    const bool na = (y >= ND/128);
    long arow; float* Cf; const float* resid; const bf16 *BH,*BL; const float* bias; int m0;
    if (!na){
        arow = (long)z*ND; m0 = y*128;
        Cf = out_nd + (long)z*ND*C; resid = detect + (long)z*ND*C;
        BH = m2sH + (long)z*CI*C; BL = m2sL + (long)z*CI*C; bias = bvq;
    } else {
        arow = (long)RD + (long)z*NA; m0 = (y - ND/128)*128;
        Cf = out_na + (long)z*NA*C; resid = aim + (long)z*NA*C;
        BH = m1sH + (long)z*CI*C; BL = m1sL + (long)z*CI*C; bias = bvw;
    }
    gemm_body<5,false,false>(dpH + arow*512 + 256, dpL + arow*512 + 256,
        BH,BL, Cf,nullptr,nullptr, bias, resid, 0.f,
        CI, 512,C,C, m0, blockIdx.x*128, blockIdx.x*128);
}

// one launch splits BOTH inputs into the contiguous [det|aim] buffer
__global__ __launch_bounds__(256) void insplit(const float* __restrict__ det,
                                               const float* __restrict__ aim,
                                               bf16* __restrict__ h, bf16* __restrict__ l){
    const long i = (long)blockIdx.x*256 + threadIdx.x;      // over RT*C/4
    if (i >= (long)RT*C/4) return;
    const long dlim = (long)RD*C/4;
    const float4 v = (i < dlim) ? ((const float4*)det)[i] : ((const float4*)aim)[i - dlim];
    const float f[4] = {v.x,v.y,v.z,v.w};
    bf16 hh[4], ll[4];
#pragma unroll
    for (int j=0;j<4;j++){
        hh[j] = __float2bfloat16_rn(f[j]);
        ll[j] = __float2bfloat16_rn(f[j] - __bfloat162float(hh[j]));
    }
    ((uint2*)h)[i] = *(uint2*)hh;
    ((uint2*)l)[i] = *(uint2*)ll;
}

struct SplitPack { const float* s[5]; bf16* h[5]; bf16* l[5]; };
__global__ __launch_bounds__(256) void fsplitN(SplitPack p, int n4){
    const int a = blockIdx.y;
    const int i = blockIdx.x*256 + threadIdx.x;
    if (i >= n4) return;
    const float4 v = ((const float4*)p.s[a])[i];
    const float f[4] = {v.x,v.y,v.z,v.w};
    bf16 hh[4], ll[4];
#pragma unroll
    for (int j=0;j<4;j++){
        hh[j] = __float2bfloat16_rn(f[j]);
        ll[j] = __float2bfloat16_rn(f[j] - __bfloat162float(hh[j]));
    }
    ((uint2*)p.h[a])[i] = *(uint2*)hh;
    ((uint2*)p.l[a])[i] = *(uint2*)ll;
}

__global__ void reduce8b2(const float* __restrict__ pa, bf16* __restrict__ oha, bf16* __restrict__ ola,
                          const float* __restrict__ pb, bf16* __restrict__ ohb, bf16* __restrict__ olb){
    const int nper = CI*CI;
    const int i = blockIdx.x*blockDim.x + threadIdx.x;
    if (i >= BATCH*nper) return;
    const int b = i/nper, r = i - b*nper;
    const float* p = (blockIdx.y ? pb : pa) + (long)b*SPLITK*nper + r;
    float s = 0.f;
#pragma unroll
    for (int k=0;k<SPLITK;k++) s += p[(long)k*nper];
    const bf16 h = __float2bfloat16_rn(s);
    if (blockIdx.y){ ohb[i] = h; olb[i] = __float2bfloat16_rn(s - __bfloat162float(h)); }
    else           { oha[i] = h; ola[i] = __float2bfloat16_rn(s - __bfloat162float(h)); }
}

__global__ void prep(const float* gw,const float* betw,const float* mw,const float* vw,const float* bw,
                     const float* gq,const float* betq,const float* mq,const float* vq,const float* bq,
                     float* svw,float* bvw,float* svq,float* bvq){
    const int i = threadIdx.x;  // 512
    const float s = gw[i]*rsqrtf(vw[i]+EPS);
    svw[i] = s; bvw[i] = (bw[i]-mw[i])*s + betw[i];
    const float t = gq[i]*rsqrtf(vq[i]+EPS);
    svq[i] = t; bvq[i] = (bq[i]-mq[i])*t + betq[i];
}

#define SYM(p, s) cudaGetSymbolAddress((void**)&p, s)

extern "C" void kernel_launch(void* const* d_in, const int* in_sizes, int n_in,
                              void* d_out, int out_size){
    (void)in_sizes; (void)n_in; (void)out_size;
    const float* detect=(const float*)d_in[0];
    const float* aim   =(const float*)d_in[1];
    const float* Wg=(const float*)d_in[2];  const float* bg=(const float*)d_in[3];
    const float* Wt=(const float*)d_in[4];  const float* bt=(const float*)d_in[5];
    const float* Wp=(const float*)d_in[6];  const float* bp=(const float*)d_in[7];
    const float* Ww=(const float*)d_in[8];  const float* bw=(const float*)d_in[9];
    const float* gw=(const float*)d_in[10]; const float* betw=(const float*)d_in[11];
    const float* mw=(const float*)d_in[12]; const float* vw=(const float*)d_in[13];
    const float* Wq=(const float*)d_in[14]; const float* bq=(const float*)d_in[15];
    const float* gq=(const float*)d_in[16]; const float* betq=(const float*)d_in[17];
    const float* mq=(const float*)d_in[18]; const float* vq=(const float*)d_in[19];

    float* out    = (float*)d_out;
    float* out_na = out;
    float* out_nd = out + (long)RA*C;

    bf16 *inH,*inL,*WgH,*WgL,*WtH,*WtL,*WpH,*WpL,*WwH,*WwL,*WqH,*WqL;
    bf16 *dpH,*dpL,*m1H,*m1L,*m2H,*m2L,*m1sH,*m1sL,*m2sH,*m2sL;
    float *p1,*p2,*svw,*bvw,*svq,*bvq;
    SYM(inH,g_inH); SYM(inL,g_inL);
    SYM(WgH,g_WgH); SYM(WgL,g_WgL); SYM(WtH,g_WtH); SYM(WtL,g_WtL);
    SYM(WpH,g_WpH); SYM(WpL,g_WpL); SYM(WwH,g_WwH); SYM(WwL,g_WwL);
    SYM(WqH,g_WqH); SYM(WqL,g_WqL);
    SYM(dpH,g_dpH); SYM(dpL,g_dpL);
    SYM(m1H,g_m1H); SYM(m1L,g_m1L); SYM(m2H,g_m2H); SYM(m2L,g_m2L);
    SYM(m1sH,g_m1sH); SYM(m1sL,g_m1sL); SYM(m2sH,g_m2sH); SYM(m2sL,g_m2sL);
    SYM(p1,g_p1); SYM(p2,g_p2);
    SYM(svw,g_svw); SYM(bvw,g_bvw); SYM(svq,g_svq); SYM(bvq,g_bvq);

    cudaFuncSetAttribute(k_proj, cudaFuncAttributeMaxDynamicSharedMemorySize, SMEM_BYTES);
    cudaFuncSetAttribute(k_gram, cudaFuncAttributeMaxDynamicSharedMemorySize, SMEM_BYTES);
    cudaFuncSetAttribute(k_fold, cudaFuncAttributeMaxDynamicSharedMemorySize, SMEM_BYTES);
    cudaFuncSetAttribute(k_out,  cudaFuncAttributeMaxDynamicSharedMemorySize, SMEM_BYTES);

    const dim3 blk(256);

    // #1 merged input split, #2 weights, #3 prep, #4 PROJ (ncu target)
    insplit<<<(int)(((long)RT*C/4+255)/256), 256>>>(detect, aim, inH, inL);
    {
        SplitPack sp{{Wg,Wp,Wt,Ww,Wq},{WgH,WpH,WtH,WwH,WqH},{WgL,WpL,WtL,WwL,WqL}};
        fsplitN<<<dim3((C*CI/4+255)/256,5), 256>>>(sp, C*CI/4);
    }
    prep<<<1,512>>>(gw,betw,mw,vw,bw, gq,betq,mq,vq,bq, svw,bvw,svq,bvq);

    k_proj<<<dim3(4, RT/128, 1), blk, SMEM_BYTES>>>(inH,inL, WgH,WgL, WpH,WpL, WtH,WtL,
        dpH,dpL, bg,bp,bt);

    k_gram<<<dim3(2,2,2*BATCH*SPLITK), blk, SMEM_BYTES>>>(dpH,dpL, p1,p2);
    reduce8b2<<<dim3((BATCH*CI*CI+255)/256,2),256>>>(p1,m1H,m1L, p2,m2H,m2L);

    k_fold<<<dim3(4,2,2*BATCH), blk, SMEM_BYTES>>>(m1H,m1L,m2H,m2L,
        WwH,WwL,WqH,WqL, m1sH,m1sL,m2sH,m2sL, svw,svq);

    k_out<<<dim3(4, ND/128 + NA/128, BATCH), blk, SMEM_BYTES>>>(dpH,dpL,
        m1sH,m1sL,m2sH,m2sL, out_na,out_nd, aim,detect, bvw,bvq);
}

// round 16
// speedup vs baseline: 1.2507x; 1.0068x over previous
#include <cuda_runtime.h>
#include <cuda_bf16.h>
#include <cstdint>

using bf16 = __nv_bfloat16;

namespace {
constexpr int BATCH=8, NA=1024, ND=4096, C=512, CI=256;
constexpr int RA=BATCH*NA, RD=BATCH*ND;
constexpr int RT=RD+RA;                    // 40960 concat rows [det|aim]
constexpr float EPS=1e-3f;
constexpr int SPLITK=8;
constexpr int NSTAGE=5;
constexpr int STAGE_B = 16384;             // k16 stage: AH4K|AL4K|BH4K|BL4K
constexpr int SMEM_BYTES = NSTAGE*STAGE_B; // 80KB
}

// ---- bf16 hi/lo split buffers (bss) ----
__device__ __align__(16) bf16 g_inH[(long)RT*C],  g_inL[(long)RT*C];    // [det|aim]
__device__ __align__(16) bf16 g_WgH[C*CI], g_WgL[C*CI];
__device__ __align__(16) bf16 g_WtH[C*CI], g_WtL[C*CI];
__device__ __align__(16) bf16 g_WpH[C*CI], g_WpL[C*CI];
__device__ __align__(16) bf16 g_WwH[CI*C], g_WwL[CI*C];
__device__ __align__(16) bf16 g_WqH[CI*C], g_WqL[CI*C];
__device__ __align__(16) bf16 g_dpH[(long)RT*512], g_dpL[(long)RT*512]; // [dx|ph] / [ax|th]
__device__ __align__(16) float g_p1[(long)BATCH*SPLITK*CI*CI];
__device__ __align__(16) float g_p2[(long)BATCH*SPLITK*CI*CI];
__device__ __align__(16) bf16 g_m1H[(long)BATCH*CI*CI], g_m1L[(long)BATCH*CI*CI];
__device__ __align__(16) bf16 g_m2H[(long)BATCH*CI*CI], g_m2L[(long)BATCH*CI*CI];
__device__ __align__(16) bf16 g_m1sH[(long)BATCH*CI*C], g_m1sL[(long)BATCH*CI*C];
__device__ __align__(16) bf16 g_m2sH[(long)BATCH*CI*C], g_m2sL[(long)BATCH*CI*C];

__device__ __forceinline__ void mma_bf16(float* c, const uint32_t* a, uint32_t b0, uint32_t b1){
    asm volatile("mma.sync.aligned.m16n8k16.row.col.f32.bf16.bf16.f32 "
        "{%0,%1,%2,%3},{%4,%5,%6,%7},{%8,%9},{%0,%1,%2,%3};\n"
        : "+f"(c[0]),"+f"(c[1]),"+f"(c[2]),"+f"(c[3])
        : "r"(a[0]),"r"(a[1]),"r"(a[2]),"r"(a[3]),"r"(b0),"r"(b1));
}
__device__ __forceinline__ void ldsm4(uint32_t* r, uint32_t a){
    asm volatile("ldmatrix.sync.aligned.m8n8.x4.shared.b16 {%0,%1,%2,%3},[%4];"
        : "=r"(r[0]),"=r"(r[1]),"=r"(r[2]),"=r"(r[3]) : "r"(a));
}
__device__ __forceinline__ void ldsm4t(uint32_t* r, uint32_t a){
    asm volatile("ldmatrix.sync.aligned.m8n8.x4.trans.shared.b16 {%0,%1,%2,%3},[%4];"
        : "=r"(r[0]),"=r"(r[1]),"=r"(r[2]),"=r"(r[3]) : "r"(a));
}
__device__ __forceinline__ void cpa16(uint32_t dst, const void* src){
    asm volatile("cp.async.cg.shared.global [%0], [%1], 16;" :: "r"(dst),"l"(src));
}
#define CP_COMMIT() asm volatile("cp.async.commit_group;")
#define CP_WAIT3()  asm volatile("cp.async.wait_group 3;")

// CTA tile 128x128, k-chunk 16, 5 stages, 8 warps (4x2), warp tile 32x64.
// MODE: 1 v+=biasv[col]
//       2 v*=scale
//       4 v*= e3[col]*rsqrt(e4[col]+EPS)                       (BN scale inline)
//       5 v+= (e1[col]-e2[col])*(e3[col]*rsqrt(e4[col]+EPS)) + biasv[col] + resid[gidx]
template<int MODE, bool TA, bool OUTB>
__device__ __forceinline__ void gemm_body(
    const bf16* __restrict__ AH, const bf16* __restrict__ AL,
    const bf16* __restrict__ BH, const bf16* __restrict__ BL,
    float* __restrict__ Cf, bf16* __restrict__ CH, bf16* __restrict__ CL,
    const float* __restrict__ biasv, const float* __restrict__ resid, float scale,
    const float* __restrict__ e1, const float* __restrict__ e2,
    const float* __restrict__ e3, const float* __restrict__ e4,
    int K, long lda, long ldb, long ldc, int m0, int n0, int nB)
{
    extern __shared__ __align__(128) char smem[];
    const int tid=threadIdx.x, lane=tid&31, warp=tid>>5;
    const uint32_t sb = (uint32_t)__cvta_generic_to_shared(smem);

    const bf16 *pAH, *pAL;
    uint32_t dA; long stepA;
    if (!TA){
        const int row=tid>>1, k8=tid&1;
        const long o = (long)(m0+row)*lda + k8*8;
        pAH = AH+o; pAL = AL+o;
        dA = (uint32_t)(row*2 + (k8 ^ ((row>>2)&1)))*16;
        stepA = 16;
    } else {
        const int k=tid>>4, m8=tid&15;
        const long o = (long)k*lda + m0 + m8*8;
        pAH = AH+o; pAL = AL+o;
        dA = (uint32_t)(k*16 + (m8 ^ (k&7)))*16;
        stepA = 16*lda;
    }
    const int kb=tid>>4, n8=tid&15;
    const long oB = (long)kb*ldb + nB + n8*8;
    const bf16 *pBH = BH+oB, *pBL = BL+oB;
    const uint32_t dB = (uint32_t)(kb*16 + (n8 ^ (kb&7)))*16;
    const long stepB = 16*ldb;

    const int wm0 = (warp>>1)*32, wn0 = (warp&1)*64;
    const int g = lane>>3;
    int aCh[2];
#pragma unroll
    for (int mt=0; mt<2; mt++){
        if (!TA){
            const int row = wm0 + mt*16 + (lane&7) + (g&1)*8;
            aCh[mt] = row*2 + ((g>>1) ^ ((row>>2)&1));
        } else {
            const int row = (lane&7) + (g>>1)*8;
            const int c = ((wm0 + mt*16)>>3) + (g&1);
            aCh[mt] = row*16 + (c ^ (row&7));
        }
    }
    int bCh[4];
#pragma unroll
    for (int np=0; np<4; np++){
        const int row = (lane&7) + (g&1)*8;
        const int c = ((wn0 + np*16)>>3) + (g>>1);
        bCh[np] = row*16 + (c ^ (row&7));
    }

    float acc[2][8][4];
#pragma unroll
    for (int mt=0;mt<2;mt++)
#pragma unroll
        for (int nt=0;nt<8;nt++)
#pragma unroll
            for (int i=0;i<4;i++) acc[mt][nt][i]=0.f;

    const int NC = K>>4;
#pragma unroll
    for (int c=0; c<4; c++){
        const uint32_t ba = sb + c*STAGE_B;
        cpa16(ba         + dA, pAH + (long)c*stepA);
        cpa16(ba + 4096  + dA, pAL + (long)c*stepA);
        cpa16(ba + 8192  + dB, pBH + (long)c*stepB);
        cpa16(ba + 12288 + dB, pBL + (long)c*stepB);
        CP_COMMIT();
    }

    int sidx = 0, fidx = 4;
#pragma unroll 1
    for (int c=0; c<NC; c++){
        CP_WAIT3();
        __syncthreads();
        if (c+4 < NC){
            const uint32_t ba = sb + fidx*STAGE_B;
            cpa16(ba         + dA, pAH + (long)(c+4)*stepA);
            cpa16(ba + 4096  + dA, pAL + (long)(c+4)*stepA);
            cpa16(ba + 8192  + dB, pBH + (long)(c+4)*stepB);
            cpa16(ba + 12288 + dB, pBL + (long)(c+4)*stepB);
        }
        CP_COMMIT();

        const uint32_t ba = sb + sidx*STAGE_B;
        uint32_t Ah[2][4], Al[2][4];
#pragma unroll
        for (int mt=0; mt<2; mt++){
            if (!TA){
                ldsm4 (Ah[mt], ba + aCh[mt]*16);
                ldsm4 (Al[mt], ba + 4096 + aCh[mt]*16);
            } else {
                ldsm4t(Ah[mt], ba + aCh[mt]*16);
                ldsm4t(Al[mt], ba + 4096 + aCh[mt]*16);
            }
        }
#pragma unroll
        for (int np=0; np<4; np++){
            uint32_t Bh[4], Bl[4];
            ldsm4t(Bh, ba + 8192  + bCh[np]*16);
            ldsm4t(Bl, ba + 12288 + bCh[np]*16);
            const int n2 = np*2;
#pragma unroll
            for (int mt=0; mt<2; mt++){
                mma_bf16(acc[mt][n2],   Ah[mt], Bh[0], Bh[1]);
                mma_bf16(acc[mt][n2+1], Ah[mt], Bh[2], Bh[3]);
                mma_bf16(acc[mt][n2],   Ah[mt], Bl[0], Bl[1]);
                mma_bf16(acc[mt][n2+1], Ah[mt], Bl[2], Bl[3]);
                mma_bf16(acc[mt][n2],   Al[mt], Bh[0], Bh[1]);
                mma_bf16(acc[mt][n2+1], Al[mt], Bh[2], Bh[3]);
            }
        }
        sidx = (sidx+1 == NSTAGE) ? 0 : sidx+1;
        fidx = (fidx+1 == NSTAGE) ? 0 : fidx+1;
    }

    const int rbase = m0 + wm0 + (lane>>2);
    const int cbase = n0 + wn0 + (lane&3)*2;
#pragma unroll
    for (int mt=0; mt<2; mt++){
#pragma unroll
        for (int nt=0; nt<8; nt++){
            const int col = cbase + nt*8;
#pragma unroll
            for (int hf=0; hf<2; hf++){
                const int row = rbase + mt*16 + hf*8;
                float v0 = acc[mt][nt][hf*2];
                float v1 = acc[mt][nt][hf*2+1];
                const long gidx = (long)row*ldc + col;
                if (MODE==1){ v0 += biasv[col]; v1 += biasv[col+1]; }
                if (MODE==2){ v0 *= scale; v1 *= scale; }
                if (MODE==4){
                    v0 *= e3[col]  *rsqrtf(e4[col]  +EPS);
                    v1 *= e3[col+1]*rsqrtf(e4[col+1]+EPS);
                }
                if (MODE==5){
                    const float2 rr = *(const float2*)&resid[gidx];
                    const float s0 = e3[col]  *rsqrtf(e4[col]  +EPS);
                    const float s1 = e3[col+1]*rsqrtf(e4[col+1]+EPS);
                    v0 += (e1[col]  -e2[col])  *s0 + biasv[col]   + rr.x;
                    v1 += (e1[col+1]-e2[col+1])*s1 + biasv[col+1] + rr.y;
                }
                if (OUTB){
                    const bf16 h0 = __float2bfloat16_rn(v0);
                    const bf16 h1 = __float2bfloat16_rn(v1);
                    const bf16 l0 = __float2bfloat16_rn(v0 - __bfloat162float(h0));
                    const bf16 l1 = __float2bfloat16_rn(v1 - __bfloat162float(h1));
                    __nv_bfloat162 hp = {h0,h1}, lp = {l0,l1};
                    *(uint32_t*)&CH[gidx] = *(uint32_t*)&hp;
                    *(uint32_t*)&CL[gidx] = *(uint32_t*)&lp;
                } else {
                    *(float2*)&Cf[gidx] = make_float2(v0, v1);
                }
            }
        }
    }
}

// merged projection: [dx|ph / ax|th] = [det|aim] @ {Wg, Wp-or-Wt} + bias
__global__ __launch_bounds__(256,2) void k_proj(
    const bf16* __restrict__ inH, const bf16* __restrict__ inL,
    const bf16* __restrict__ WgH, const bf16* __restrict__ WgL,
    const bf16* __restrict__ WpH, const bf16* __restrict__ WpL,
    const bf16* __restrict__ WtH, const bf16* __restrict__ WtL,
    bf16* dpH, bf16* dpL,
    const float* bg, const float* bp, const float* bt)
{
    const int y = blockIdx.y, n0 = blockIdx.x*128;
    const bool aimrow = (y >= RD/128);
    const bf16 *BH, *BL; const float* bias;
    if (n0 < 256){ BH=WgH; BL=WgL; bias=bg; }
    else if (!aimrow){ BH=WpH; BL=WpL; bias=bp-256; }
    else { BH=WtH; BL=WtL; bias=bt-256; }
    const int nB = (n0<256)? n0 : n0-256;
    gemm_body<1,false,true>(inH,inL, BH,BL, nullptr,dpH,dpL,
        bias,nullptr,0.f, nullptr,nullptr,nullptr,nullptr,
        C, C,CI,512, y*128, n0, nB);
}

// merged gram: m1 = ph^T dx / ND (z<64), m2 = th^T ax / NA (z>=64), SPLITK=8
__global__ __launch_bounds__(256,2) void k_gram(
    const bf16* __restrict__ dpH, const bf16* __restrict__ dpL,
    float* p1, float* p2)
{
    const int z = blockIdx.z;
    const bool is2 = (z >= BATCH*SPLITK);
    const int zz = is2? z-BATCH*SPLITK : z;
    const int b = zz/SPLITK, s = zz%SPLITK;
    long arow; int K; float* P; float scale;
    if (!is2){ arow = (long)b*ND + (long)s*(ND/SPLITK); K = ND/SPLITK; P = p1; scale = 1.f/(float)ND; }
    else     { arow = (long)RD + (long)b*NA + (long)s*(NA/SPLITK); K = NA/SPLITK; P = p2; scale = 1.f/(float)NA; }
    gemm_body<2,true,false>(dpH + arow*512 + 256, dpL + arow*512 + 256,
        dpH + arow*512, dpL + arow*512,
        P + (long)zz*CI*CI, nullptr, nullptr,
        nullptr,nullptr, scale, nullptr,nullptr,nullptr,nullptr,
        K, 512,512,CI,
        blockIdx.y*128, blockIdx.x*128, blockIdx.x*128);
}

// merged fold: m1s = (m1 @ Ww)*(gw*rsqrt(vw+EPS)) (z<8), m2s analog (z>=8)
__global__ __launch_bounds__(256,2) void k_fold(
    const bf16* m1H,const bf16* m1L,const bf16* m2H,const bf16* m2L,
    const bf16* WwH,const bf16* WwL,const bf16* WqH,const bf16* WqL,
    bf16* m1sH,bf16* m1sL,bf16* m2sH,bf16* m2sL,
    const float* gw,const float* vw,const float* gq,const float* vq)
{
    const int z = blockIdx.z;
    const bool q = (z >= BATCH);
    const int b = q? z-BATCH : z;
    const long aoff = (long)b*CI*CI, coff = (long)b*CI*C;
    gemm_body<4,false,true>(
        (q?m2H:m1H)+aoff, (q?m2L:m1L)+aoff,
        q?WqH:WwH, q?WqL:WwL,
        nullptr, (q?m2sH:m1sH)+coff, (q?m2sL:m1sL)+coff,
        nullptr, nullptr, 0.f,
        nullptr,nullptr, q?gq:gw, q?vq:vw,
        CI, CI,C,C,
        blockIdx.y*128, blockIdx.x*128, blockIdx.x*128);
}

// merged outputs: y<32: out_nd = ph@m2s + BN-bias + detect ; y>=32: out_na = th@m1s + BN-bias + aim
__global__ __launch_bounds__(256,2) void k_out(
    const bf16* __restrict__ dpH, const bf16* __restrict__ dpL,
    const bf16* m1sH,const bf16* m1sL,const bf16* m2sH,const bf16* m2sL,
    float* out_na, float* out_nd, const float* aim, const float* detect,
    const float* bw,const float* mw,const float* gw,const float* vw,const float* betw,
    const float* bq,const float* mq,const float* gq,const float* vq,const float* betq)
{
    const int z = blockIdx.z, y = blockIdx.y;
    const bool na = (y >= ND/128);
    long arow; float* Cf; const float* resid; const bf16 *BH,*BL; int m0;
    const float *pe1,*pe2,*pe3,*pe4,*pbv;
    if (!na){
        arow = (long)z*ND; m0 = y*128;
        Cf = out_nd + (long)z*ND*C; resid = detect + (long)z*ND*C;
        BH = m2sH + (long)z*CI*C; BL = m2sL + (long)z*CI*C;
        pe1=bq; pe2=mq; pe3=gq; pe4=vq; pbv=betq;
    } else {
        arow = (long)RD + (long)z*NA; m0 = (y - ND/128)*128;
        Cf = out_na + (long)z*NA*C; resid = aim + (long)z*NA*C;
        BH = m1sH + (long)z*CI*C; BL = m1sL + (long)z*CI*C;
        pe1=bw; pe2=mw; pe3=gw; pe4=vw; pbv=betw;
    }
    gemm_body<5,false,false>(dpH + arow*512 + 256, dpL + arow*512 + 256,
        BH,BL, Cf,nullptr,nullptr, pbv, resid, 0.f,
        pe1,pe2,pe3,pe4,
        CI, 512,C,C, m0, blockIdx.x*128, blockIdx.x*128);
}

// one launch splits BOTH inputs into the contiguous [det|aim] buffer
__global__ __launch_bounds__(256) void insplit(const float* __restrict__ det,
                                               const float* __restrict__ aim,
                                               bf16* __restrict__ h, bf16* __restrict__ l){
    const long i = (long)blockIdx.x*256 + threadIdx.x;      // over RT*C/4
    if (i >= (long)RT*C/4) return;
    const long dlim = (long)RD*C/4;
    const float4 v = (i < dlim) ? ((const float4*)det)[i] : ((const float4*)aim)[i - dlim];
    const float f[4] = {v.x,v.y,v.z,v.w};
    bf16 hh[4], ll[4];
#pragma unroll
    for (int j=0;j<4;j++){
        hh[j] = __float2bfloat16_rn(f[j]);
        ll[j] = __float2bfloat16_rn(f[j] - __bfloat162float(hh[j]));
    }
    ((uint2*)h)[i] = *(uint2*)hh;
    ((uint2*)l)[i] = *(uint2*)ll;
}

struct SplitPack { const float* s[5]; bf16* h[5]; bf16* l[5]; };
__global__ __launch_bounds__(256) void fsplitN(SplitPack p, int n4){
    const int a = blockIdx.y;
    const int i = blockIdx.x*256 + threadIdx.x;
    if (i >= n4) return;
    const float4 v = ((const float4*)p.s[a])[i];
    const float f[4] = {v.x,v.y,v.z,v.w};
    bf16 hh[4], ll[4];
#pragma unroll
    for (int j=0;j<4;j++){
        hh[j] = __float2bfloat16_rn(f[j]);
        ll[j] = __float2bfloat16_rn(f[j] - __bfloat162float(hh[j]));
    }
    ((uint2*)p.h[a])[i] = *(uint2*)hh;
    ((uint2*)p.l[a])[i] = *(uint2*)ll;
}

__global__ void reduce8b2(const float* __restrict__ pa, bf16* __restrict__ oha, bf16* __restrict__ ola,
                          const float* __restrict__ pb, bf16* __restrict__ ohb, bf16* __restrict__ olb){
    const int nper = CI*CI;
    const int i = blockIdx.x*blockDim.x + threadIdx.x;
    if (i >= BATCH*nper) return;
    const int b = i/nper, r = i - b*nper;
    const float* p = (blockIdx.y ? pb : pa) + (long)b*SPLITK*nper + r;
    float s = 0.f;
#pragma unroll
    for (int k=0;k<SPLITK;k++) s += p[(long)k*nper];
    const bf16 h = __float2bfloat16_rn(s);
    if (blockIdx.y){ ohb[i] = h; olb[i] = __float2bfloat16_rn(s - __bfloat162float(h)); }
    else           { oha[i] = h; ola[i] = __float2bfloat16_rn(s - __bfloat162float(h)); }
}

#define SYM(p, s) cudaGetSymbolAddress((void**)&p, s)

extern "C" void kernel_launch(void* const* d_in, const int* in_sizes, int n_in,
                              void* d_out, int out_size){
    (void)in_sizes; (void)n_in; (void)out_size;
    const float* detect=(const float*)d_in[0];
    const float* aim   =(const float*)d_in[1];
    const float* Wg=(const float*)d_in[2];  const float* bg=(const float*)d_in[3];
    const float* Wt=(const float*)d_in[4];  const float* bt=(const float*)d_in[5];
    const float* Wp=(const float*)d_in[6];  const float* bp=(const float*)d_in[7];
    const float* Ww=(const float*)d_in[8];  const float* bw=(const float*)d_in[9];
    const float* gw=(const float*)d_in[10]; const float* betw=(const float*)d_in[11];
    const float* mw=(const float*)d_in[12]; const float* vw=(const float*)d_in[13];
    const float* Wq=(const float*)d_in[14]; const float* bq=(const float*)d_in[15];
    const float* gq=(const float*)d_in[16]; const float* betq=(const float*)d_in[17];
    const float* mq=(const float*)d_in[18]; const float* vq=(const float*)d_in[19];

    float* out    = (float*)d_out;
    float* out_na = out;
    float* out_nd = out + (long)RA*C;

    bf16 *inH,*inL,*WgH,*WgL,*WtH,*WtL,*WpH,*WpL,*WwH,*WwL,*WqH,*WqL;
    bf16 *dpH,*dpL,*m1H,*m1L,*m2H,*m2L,*m1sH,*m1sL,*m2sH,*m2sL;
    float *p1,*p2;
    SYM(inH,g_inH); SYM(inL,g_inL);
    SYM(WgH,g_WgH); SYM(WgL,g_WgL); SYM(WtH,g_WtH); SYM(WtL,g_WtL);
    SYM(WpH,g_WpH); SYM(WpL,g_WpL); SYM(WwH,g_WwH); SYM(WwL,g_WwL);
    SYM(WqH,g_WqH); SYM(WqL,g_WqL);
    SYM(dpH,g_dpH); SYM(dpL,g_dpL);
    SYM(m1H,g_m1H); SYM(m1L,g_m1L); SYM(m2H,g_m2H); SYM(m2L,g_m2L);
    SYM(m1sH,g_m1sH); SYM(m1sL,g_m1sL); SYM(m2sH,g_m2sH); SYM(m2sL,g_m2sL);
    SYM(p1,g_p1); SYM(p2,g_p2);

    cudaFuncSetAttribute(k_proj, cudaFuncAttributeMaxDynamicSharedMemorySize, SMEM_BYTES);
    cudaFuncSetAttribute(k_gram, cudaFuncAttributeMaxDynamicSharedMemorySize, SMEM_BYTES);
    cudaFuncSetAttribute(k_fold, cudaFuncAttributeMaxDynamicSharedMemorySize, SMEM_BYTES);
    cudaFuncSetAttribute(k_out,  cudaFuncAttributeMaxDynamicSharedMemorySize, SMEM_BYTES);

    const dim3 blk(256);

    // #1 merged input split, #2 weights, #3 PROJ, #4 GRAM (ncu target this round)
    insplit<<<(int)(((long)RT*C/4+255)/256), 256>>>(detect, aim, inH, inL);
    {
        SplitPack sp{{Wg,Wp,Wt,Ww,Wq},{WgH,WpH,WtH,WwH,WqH},{WgL,WpL,WtL,WwL,WqL}};
        fsplitN<<<dim3((C*CI/4+255)/256,5), 256>>>(sp, C*CI/4);
    }

    k_proj<<<dim3(4, RT/128, 1), blk, SMEM_BYTES>>>(inH,inL, WgH,WgL, WpH,WpL, WtH,WtL,
        dpH,dpL, bg,bp,bt);

    k_gram<<<dim3(2,2,2*BATCH*SPLITK), blk, SMEM_BYTES>>>(dpH,dpL, p1,p2);
    reduce8b2<<<dim3((BATCH*CI*CI+255)/256,2),256>>>(p1,m1H,m1L, p2,m2H,m2L);

    k_fold<<<dim3(4,2,2*BATCH), blk, SMEM_BYTES>>>(m1H,m1L,m2H,m2L,
        WwH,WwL,WqH,WqL, m1sH,m1sL,m2sH,m2sL, gw,vw,gq,vq);

    k_out<<<dim3(4, ND/128 + NA/128, BATCH), blk, SMEM_BYTES>>>(dpH,dpL,
        m1sH,m1sL,m2sH,m2sL, out_na,out_nd, aim,detect,
        bw,mw,gw,vw,betw, bq,mq,gq,vq,betq);
}